// round 14
// baseline (speedup 1.0000x reference)
#include <cuda_runtime.h>
#include <cstdint>

// Problem dims
#define Bv 32
#define Cv 1024
#define Nv 784
#define Mv 4
#define N4v 196      // Nv/4
#define GR 8         // rows per generation
#define GEN 16       // generations per block
#define BROWS 128    // GR*GEN rows per block
#define CHUNKS 8     // Cv/BROWS
#define GSZ (GR * N4v)   // 1568 float4 per generation buffer

// Scratch (device globals)
__device__ float  g_invnorm[Bv][Cv];
__device__ float4 g_tpart[Bv][CHUNKS][Mv][N4v];  // per-chunk partials (3.2 MB)
__device__ float4 g_h[Bv][N4v];                  // h[b,n] = sum_m g/s

__device__ __forceinline__ void cp_async16(uint32_t saddr, const void* gaddr) {
    asm volatile("cp.async.cg.shared.global [%0], [%1], 16;\n" :: "r"(saddr), "l"(gaddr));
}
__device__ __forceinline__ void cp_commit() {
    asm volatile("cp.async.commit_group;\n");
}
template <int N>
__device__ __forceinline__ void cp_wait() {
    asm volatile("cp.async.wait_group %0;\n" :: "n"(N));
}

extern __shared__ float4 smem_dyn[];  // 2 * GSZ float4 = 50176 B

// ---------------------------------------------------------------------------
// kAB: block = (b, 128-row chunk), 16 generations of 8 rows, double-buffered
// cp.async (proven pipeline). Per gen: warp-per-row norms from smem, then
// thread-per-quad 8-row accumulate. Plain STG flush of 12.5 KB partials
// (NO atomics — removes the L2 atomic tail).
// ---------------------------------------------------------------------------
__global__ void __launch_bounds__(256) kAB(const float* __restrict__ x,
                                           const float* __restrict__ Wm) {
    __shared__ float4 swsc[GR];
    int b = blockIdx.x, ch = blockIdx.y;
    int p0 = ch * BROWS;
    int t = threadIdx.x;
    int warp = t >> 5, lane = t & 31;
    const float4* base = reinterpret_cast<const float4*>(x) + ((size_t)b * Cv + p0) * N4v;
    uint32_t sbase = (uint32_t)__cvta_generic_to_shared(smem_dyn);

    // prefetch generation 0 into buffer 0
#pragma unroll
    for (int k = 0; k < 7; ++k) {
        int i = t + k * 256;
        if (i < GSZ) cp_async16(sbase + i * 16u, base + i);
    }
    cp_commit();

    float4 a0 = {0, 0, 0, 0}, a1 = a0, a2 = a0, a3 = a0;

#pragma unroll 4
    for (int g = 0; g < GEN; ++g) {
        if (g + 1 < GEN) {
            uint32_t sb = sbase + ((g + 1) & 1) * (GSZ * 16u);
            const float4* gb = base + (g + 1) * GSZ;
#pragma unroll
            for (int k = 0; k < 7; ++k) {
                int i = t + k * 256;
                if (i < GSZ) cp_async16(sb + i * 16u, gb + i);
            }
            cp_commit();
            cp_wait<1>();   // current generation's data is ready
        } else {
            cp_wait<0>();
        }
        __syncthreads();

        float4* cur = smem_dyn + (g & 1) * GSZ;

        // norms: warp w handles row w (8 warps, 8 rows)
        {
            float s = 0.f;
#pragma unroll
            for (int k = 0; k < 7; ++k) {
                int idx = lane + k * 32;
                if (idx < N4v) {
                    float4 v = cur[warp * N4v + idx];
                    s += v.x * v.x + v.y * v.y + v.z * v.z + v.w * v.w;
                }
            }
#pragma unroll
            for (int o = 16; o; o >>= 1) s += __shfl_xor_sync(0xffffffffu, s, o);
            if (lane == 0) {
                float inv = 1.0f / fmaxf(sqrtf(s), 1e-10f);
                int p = p0 + g * GR + warp;
                g_invnorm[b][p] = inv;
                float4 w;
                w.x = Wm[0 * Cv + p] * inv;
                w.y = Wm[1 * Cv + p] * inv;
                w.z = Wm[2 * Cv + p] * inv;
                w.w = Wm[3 * Cv + p] * inv;
                swsc[warp] = w;
            }
        }
        __syncthreads();

        // t-accumulation for this generation's 8 rows
        if (t < N4v) {
#pragma unroll
            for (int r = 0; r < GR; ++r) {
                float4 w  = swsc[r];
                float4 xv = cur[r * N4v + t];
                a0.x = fmaf(w.x, xv.x, a0.x); a0.y = fmaf(w.x, xv.y, a0.y);
                a0.z = fmaf(w.x, xv.z, a0.z); a0.w = fmaf(w.x, xv.w, a0.w);
                a1.x = fmaf(w.y, xv.x, a1.x); a1.y = fmaf(w.y, xv.y, a1.y);
                a1.z = fmaf(w.y, xv.z, a1.z); a1.w = fmaf(w.y, xv.w, a1.w);
                a2.x = fmaf(w.z, xv.x, a2.x); a2.y = fmaf(w.z, xv.y, a2.y);
                a2.z = fmaf(w.z, xv.z, a2.z); a2.w = fmaf(w.z, xv.w, a2.w);
                a3.x = fmaf(w.w, xv.x, a3.x); a3.y = fmaf(w.w, xv.y, a3.y);
                a3.z = fmaf(w.w, xv.z, a3.z); a3.w = fmaf(w.w, xv.w, a3.w);
            }
        }
        __syncthreads();  // buffer fully consumed before next prefetch overwrites
    }

    // plain vectorized store of this block's partials (no atomics)
    if (t < N4v) {
        g_tpart[b][ch][0][t] = a0;
        g_tpart[b][ch][1][t] = a1;
        g_tpart[b][ch][2][t] = a2;
        g_tpart[b][ch][3][t] = a3;
    }
}

// ---------------------------------------------------------------------------
// kC: one block per b, 224 threads. Reduce 8 chunk partials (L2-hot, high
// MLP), sigmoid, per-model sum of g^2, h = sum_m g/s. No zeroing needed.
// ---------------------------------------------------------------------------
__global__ void __launch_bounds__(224) kC() {
    int b = blockIdx.x;
    int t = threadIdx.x;
    bool valid = (t < N4v);
    float4 gg0 = {0,0,0,0}, gg1 = gg0, gg2 = gg0, gg3 = gg0;
    if (valid) {
        float4 t0 = {0,0,0,0}, t1 = t0, t2 = t0, t3 = t0;
#pragma unroll
        for (int c = 0; c < CHUNKS; ++c) {
            float4 v0 = g_tpart[b][c][0][t];
            float4 v1 = g_tpart[b][c][1][t];
            float4 v2 = g_tpart[b][c][2][t];
            float4 v3 = g_tpart[b][c][3][t];
            t0.x += v0.x; t0.y += v0.y; t0.z += v0.z; t0.w += v0.w;
            t1.x += v1.x; t1.y += v1.y; t1.z += v1.z; t1.w += v1.w;
            t2.x += v2.x; t2.y += v2.y; t2.z += v2.z; t2.w += v2.w;
            t3.x += v3.x; t3.y += v3.y; t3.z += v3.z; t3.w += v3.w;
        }
        auto sig4 = [](float4 v) {
            float4 r;
            r.x = 1.f / (1.f + __expf(-v.x));
            r.y = 1.f / (1.f + __expf(-v.y));
            r.z = 1.f / (1.f + __expf(-v.z));
            r.w = 1.f / (1.f + __expf(-v.w));
            return r;
        };
        gg0 = sig4(t0); gg1 = sig4(t1); gg2 = sig4(t2); gg3 = sig4(t3);
    }
    float s0 = gg0.x*gg0.x + gg0.y*gg0.y + gg0.z*gg0.z + gg0.w*gg0.w;
    float s1 = gg1.x*gg1.x + gg1.y*gg1.y + gg1.z*gg1.z + gg1.w*gg1.w;
    float s2 = gg2.x*gg2.x + gg2.y*gg2.y + gg2.z*gg2.z + gg2.w*gg2.w;
    float s3 = gg3.x*gg3.x + gg3.y*gg3.y + gg3.z*gg3.z + gg3.w*gg3.w;
#pragma unroll
    for (int o = 16; o; o >>= 1) {
        s0 += __shfl_xor_sync(0xffffffffu, s0, o);
        s1 += __shfl_xor_sync(0xffffffffu, s1, o);
        s2 += __shfl_xor_sync(0xffffffffu, s2, o);
        s3 += __shfl_xor_sync(0xffffffffu, s3, o);
    }
    __shared__ float sm[4];
    if (t < 4) sm[t] = 0.f;
    __syncthreads();
    if ((t & 31) == 0) {
        atomicAdd(&sm[0], s0);
        atomicAdd(&sm[1], s1);
        atomicAdd(&sm[2], s2);
        atomicAdd(&sm[3], s3);
    }
    __syncthreads();
    if (valid) {
        float i0 = 1.f / sm[0], i1 = 1.f / sm[1], i2 = 1.f / sm[2], i3 = 1.f / sm[3];
        float4 h;
        h.x = gg0.x*i0 + gg1.x*i1 + gg2.x*i2 + gg3.x*i3;
        h.y = gg0.y*i0 + gg1.y*i1 + gg2.y*i2 + gg3.y*i3;
        h.z = gg0.z*i0 + gg1.z*i1 + gg2.z*i2 + gg3.z*i3;
        h.w = gg0.w*i0 + gg1.w*i1 + gg2.w*i2 + gg3.w*i3;
        g_h[b][t] = h;
    }
}

// ---------------------------------------------------------------------------
// kD: barrier-free final dot (proven). Grid (32, 32), 512 threads; each
// warp streams TWO rows interleaved; h via __ldg (L1-hot).
// ---------------------------------------------------------------------------
__global__ void __launch_bounds__(512) kD(const float* __restrict__ x,
                                          float* __restrict__ out) {
    int b = blockIdx.x;
    int warp = threadIdx.x >> 5, lane = threadIdx.x & 31;
    int p = (blockIdx.y << 5) + (warp << 1);   // rows p and p+1
    const float4* r0 = reinterpret_cast<const float4*>(x) + ((size_t)b * Cv + p) * N4v;
    const float4* r1 = r0 + N4v;
    const float4* hb = &g_h[b][0];
    float s0 = 0.f, s1 = 0.f;
#pragma unroll
    for (int k = 0; k < 6; ++k) {
        int idx = lane + k * 32;
        float4 a = r0[idx], c = r1[idx];
        float4 h = __ldg(hb + idx);
        s0 += a.x * h.x + a.y * h.y + a.z * h.z + a.w * h.w;
        s1 += c.x * h.x + c.y * h.y + c.z * h.z + c.w * h.w;
    }
    if (lane < 4) {
        int idx = 192 + lane;
        float4 a = r0[idx], c = r1[idx];
        float4 h = __ldg(hb + idx);
        s0 += a.x * h.x + a.y * h.y + a.z * h.z + a.w * h.w;
        s1 += c.x * h.x + c.y * h.y + c.z * h.z + c.w * h.w;
    }
#pragma unroll
    for (int o = 16; o; o >>= 1) {
        s0 += __shfl_xor_sync(0xffffffffu, s0, o);
        s1 += __shfl_xor_sync(0xffffffffu, s1, o);
    }
    if (lane == 0) {
        out[b * Cv + p]     = s0 * g_invnorm[b][p];
        out[b * Cv + p + 1] = s1 * g_invnorm[b][p + 1];
    }
}

extern "C" void kernel_launch(void* const* d_in, const int* in_sizes, int n_in,
                              void* d_out, int out_size) {
    const float* x  = (const float*)d_in[0];   // [32,1024,28,28] f32
    const float* Wm = (const float*)d_in[1];   // [4,1,1024] f32
    float* out = (float*)d_out;                // [32,1024] f32

    static const int smem_bytes = 2 * GSZ * sizeof(float4);  // 50176
    cudaFuncSetAttribute(kAB, cudaFuncAttributeMaxDynamicSharedMemorySize, smem_bytes);

    kAB<<<dim3(32, CHUNKS), 256, smem_bytes>>>(x, Wm);
    kC<<<32, 224>>>();
    kD<<<dim3(32, 32), 512>>>(x, out);
}

// round 15
// speedup vs baseline: 1.0206x; 1.0206x over previous
#include <cuda_runtime.h>
#include <cstdint>

// Problem dims
#define Bv 32
#define Cv 1024
#define Nv 784
#define Mv 4
#define N4v 196      // Nv/4
#define GR 8         // rows per generation
#define GEN 8        // generations per block
#define BROWS 64     // GR*GEN rows per block
#define CHUNKS 16    // Cv/BROWS
#define GSZ (GR * N4v)   // 1568 float4 per generation buffer

// Scratch (device globals)
__device__ float  g_invnorm[Bv][Cv];
__device__ float4 g_tpart[Bv][CHUNKS][Mv][N4v];  // per-chunk partials (6.4 MB)
__device__ float4 g_h[Bv][N4v];                  // h[b,n] = sum_m g/s

__device__ __forceinline__ void cp_async16(uint32_t saddr, const void* gaddr) {
    asm volatile("cp.async.cg.shared.global [%0], [%1], 16;\n" :: "r"(saddr), "l"(gaddr));
}
__device__ __forceinline__ void cp_commit() {
    asm volatile("cp.async.commit_group;\n");
}
template <int N>
__device__ __forceinline__ void cp_wait() {
    asm volatile("cp.async.wait_group %0;\n" :: "n"(N));
}

extern __shared__ float4 smem_dyn[];  // 2 * GSZ float4 = 50176 B

// ---------------------------------------------------------------------------
// kAB: R12's exact proven shape — block = (b, 64-row chunk), 8 generations
// of 8 rows, double-buffered cp.async, 512 blocks — but with R13's plain
// STG partial flush instead of atomics (no L2 atomic tail).
// ---------------------------------------------------------------------------
__global__ void __launch_bounds__(256) kAB(const float* __restrict__ x,
                                           const float* __restrict__ Wm) {
    __shared__ float4 swsc[GR];
    int b = blockIdx.x, ch = blockIdx.y;
    int p0 = ch * BROWS;
    int t = threadIdx.x;
    int warp = t >> 5, lane = t & 31;
    const float4* base = reinterpret_cast<const float4*>(x) + ((size_t)b * Cv + p0) * N4v;
    uint32_t sbase = (uint32_t)__cvta_generic_to_shared(smem_dyn);

    // prefetch generation 0 into buffer 0
#pragma unroll
    for (int k = 0; k < 7; ++k) {
        int i = t + k * 256;
        if (i < GSZ) cp_async16(sbase + i * 16u, base + i);
    }
    cp_commit();

    float4 a0 = {0, 0, 0, 0}, a1 = a0, a2 = a0, a3 = a0;

#pragma unroll
    for (int g = 0; g < GEN; ++g) {
        if (g + 1 < GEN) {
            uint32_t sb = sbase + ((g + 1) & 1) * (GSZ * 16u);
            const float4* gb = base + (g + 1) * GSZ;
#pragma unroll
            for (int k = 0; k < 7; ++k) {
                int i = t + k * 256;
                if (i < GSZ) cp_async16(sb + i * 16u, gb + i);
            }
            cp_commit();
            cp_wait<1>();   // current generation's data is ready
        } else {
            cp_wait<0>();
        }
        __syncthreads();

        float4* cur = smem_dyn + (g & 1) * GSZ;

        // norms: warp w handles row w (8 warps, 8 rows)
        {
            float s = 0.f;
#pragma unroll
            for (int k = 0; k < 7; ++k) {
                int idx = lane + k * 32;
                if (idx < N4v) {
                    float4 v = cur[warp * N4v + idx];
                    s += v.x * v.x + v.y * v.y + v.z * v.z + v.w * v.w;
                }
            }
#pragma unroll
            for (int o = 16; o; o >>= 1) s += __shfl_xor_sync(0xffffffffu, s, o);
            if (lane == 0) {
                float inv = 1.0f / fmaxf(sqrtf(s), 1e-10f);
                int p = p0 + g * GR + warp;
                g_invnorm[b][p] = inv;
                float4 w;
                w.x = Wm[0 * Cv + p] * inv;
                w.y = Wm[1 * Cv + p] * inv;
                w.z = Wm[2 * Cv + p] * inv;
                w.w = Wm[3 * Cv + p] * inv;
                swsc[warp] = w;
            }
        }
        __syncthreads();

        // t-accumulation for this generation's 8 rows
        if (t < N4v) {
#pragma unroll
            for (int r = 0; r < GR; ++r) {
                float4 w  = swsc[r];
                float4 xv = cur[r * N4v + t];
                a0.x = fmaf(w.x, xv.x, a0.x); a0.y = fmaf(w.x, xv.y, a0.y);
                a0.z = fmaf(w.x, xv.z, a0.z); a0.w = fmaf(w.x, xv.w, a0.w);
                a1.x = fmaf(w.y, xv.x, a1.x); a1.y = fmaf(w.y, xv.y, a1.y);
                a1.z = fmaf(w.y, xv.z, a1.z); a1.w = fmaf(w.y, xv.w, a1.w);
                a2.x = fmaf(w.z, xv.x, a2.x); a2.y = fmaf(w.z, xv.y, a2.y);
                a2.z = fmaf(w.z, xv.z, a2.z); a2.w = fmaf(w.z, xv.w, a2.w);
                a3.x = fmaf(w.w, xv.x, a3.x); a3.y = fmaf(w.w, xv.y, a3.y);
                a3.z = fmaf(w.w, xv.z, a3.z); a3.w = fmaf(w.w, xv.w, a3.w);
            }
        }
        __syncthreads();  // buffer fully consumed before next prefetch overwrites
    }

    // plain vectorized store of this block's partials (no atomics)
    if (t < N4v) {
        g_tpart[b][ch][0][t] = a0;
        g_tpart[b][ch][1][t] = a1;
        g_tpart[b][ch][2][t] = a2;
        g_tpart[b][ch][3][t] = a3;
    }
}

// ---------------------------------------------------------------------------
// kC: one block per b, 224 threads. Reduce 16 chunk partials (L2-hot, high
// MLP), sigmoid, per-model sum of g^2, h = sum_m g/s. No zeroing needed.
// ---------------------------------------------------------------------------
__global__ void __launch_bounds__(224) kC() {
    int b = blockIdx.x;
    int t = threadIdx.x;
    bool valid = (t < N4v);
    float4 gg0 = {0,0,0,0}, gg1 = gg0, gg2 = gg0, gg3 = gg0;
    if (valid) {
        float4 t0 = {0,0,0,0}, t1 = t0, t2 = t0, t3 = t0;
#pragma unroll 4
        for (int c = 0; c < CHUNKS; ++c) {
            float4 v0 = g_tpart[b][c][0][t];
            float4 v1 = g_tpart[b][c][1][t];
            float4 v2 = g_tpart[b][c][2][t];
            float4 v3 = g_tpart[b][c][3][t];
            t0.x += v0.x; t0.y += v0.y; t0.z += v0.z; t0.w += v0.w;
            t1.x += v1.x; t1.y += v1.y; t1.z += v1.z; t1.w += v1.w;
            t2.x += v2.x; t2.y += v2.y; t2.z += v2.z; t2.w += v2.w;
            t3.x += v3.x; t3.y += v3.y; t3.z += v3.z; t3.w += v3.w;
        }
        auto sig4 = [](float4 v) {
            float4 r;
            r.x = 1.f / (1.f + __expf(-v.x));
            r.y = 1.f / (1.f + __expf(-v.y));
            r.z = 1.f / (1.f + __expf(-v.z));
            r.w = 1.f / (1.f + __expf(-v.w));
            return r;
        };
        gg0 = sig4(t0); gg1 = sig4(t1); gg2 = sig4(t2); gg3 = sig4(t3);
    }
    float s0 = gg0.x*gg0.x + gg0.y*gg0.y + gg0.z*gg0.z + gg0.w*gg0.w;
    float s1 = gg1.x*gg1.x + gg1.y*gg1.y + gg1.z*gg1.z + gg1.w*gg1.w;
    float s2 = gg2.x*gg2.x + gg2.y*gg2.y + gg2.z*gg2.z + gg2.w*gg2.w;
    float s3 = gg3.x*gg3.x + gg3.y*gg3.y + gg3.z*gg3.z + gg3.w*gg3.w;
#pragma unroll
    for (int o = 16; o; o >>= 1) {
        s0 += __shfl_xor_sync(0xffffffffu, s0, o);
        s1 += __shfl_xor_sync(0xffffffffu, s1, o);
        s2 += __shfl_xor_sync(0xffffffffu, s2, o);
        s3 += __shfl_xor_sync(0xffffffffu, s3, o);
    }
    __shared__ float sm[4];
    if (t < 4) sm[t] = 0.f;
    __syncthreads();
    if ((t & 31) == 0) {
        atomicAdd(&sm[0], s0);
        atomicAdd(&sm[1], s1);
        atomicAdd(&sm[2], s2);
        atomicAdd(&sm[3], s3);
    }
    __syncthreads();
    if (valid) {
        float i0 = 1.f / sm[0], i1 = 1.f / sm[1], i2 = 1.f / sm[2], i3 = 1.f / sm[3];
        float4 h;
        h.x = gg0.x*i0 + gg1.x*i1 + gg2.x*i2 + gg3.x*i3;
        h.y = gg0.y*i0 + gg1.y*i1 + gg2.y*i2 + gg3.y*i3;
        h.z = gg0.z*i0 + gg1.z*i1 + gg2.z*i2 + gg3.z*i3;
        h.w = gg0.w*i0 + gg1.w*i1 + gg2.w*i2 + gg3.w*i3;
        g_h[b][t] = h;
    }
}

// ---------------------------------------------------------------------------
// kD: barrier-free final dot (proven). Grid (32, 32), 512 threads; each
// warp streams TWO rows interleaved; h via __ldg (L1-hot).
// ---------------------------------------------------------------------------
__global__ void __launch_bounds__(512) kD(const float* __restrict__ x,
                                          float* __restrict__ out) {
    int b = blockIdx.x;
    int warp = threadIdx.x >> 5, lane = threadIdx.x & 31;
    int p = (blockIdx.y << 5) + (warp << 1);   // rows p and p+1
    const float4* r0 = reinterpret_cast<const float4*>(x) + ((size_t)b * Cv + p) * N4v;
    const float4* r1 = r0 + N4v;
    const float4* hb = &g_h[b][0];
    float s0 = 0.f, s1 = 0.f;
#pragma unroll
    for (int k = 0; k < 6; ++k) {
        int idx = lane + k * 32;
        float4 a = r0[idx], c = r1[idx];
        float4 h = __ldg(hb + idx);
        s0 += a.x * h.x + a.y * h.y + a.z * h.z + a.w * h.w;
        s1 += c.x * h.x + c.y * h.y + c.z * h.z + c.w * h.w;
    }
    if (lane < 4) {
        int idx = 192 + lane;
        float4 a = r0[idx], c = r1[idx];
        float4 h = __ldg(hb + idx);
        s0 += a.x * h.x + a.y * h.y + a.z * h.z + a.w * h.w;
        s1 += c.x * h.x + c.y * h.y + c.z * h.z + c.w * h.w;
    }
#pragma unroll
    for (int o = 16; o; o >>= 1) {
        s0 += __shfl_xor_sync(0xffffffffu, s0, o);
        s1 += __shfl_xor_sync(0xffffffffu, s1, o);
    }
    if (lane == 0) {
        out[b * Cv + p]     = s0 * g_invnorm[b][p];
        out[b * Cv + p + 1] = s1 * g_invnorm[b][p + 1];
    }
}

extern "C" void kernel_launch(void* const* d_in, const int* in_sizes, int n_in,
                              void* d_out, int out_size) {
    const float* x  = (const float*)d_in[0];   // [32,1024,28,28] f32
    const float* Wm = (const float*)d_in[1];   // [4,1,1024] f32
    float* out = (float*)d_out;                // [32,1024] f32

    static const int smem_bytes = 2 * GSZ * sizeof(float4);  // 50176
    cudaFuncSetAttribute(kAB, cudaFuncAttributeMaxDynamicSharedMemorySize, smem_bytes);

    kAB<<<dim3(32, CHUNKS), 256, smem_bytes>>>(x, Wm);
    kC<<<32, 224>>>();
    kD<<<dim3(32, 32), 512>>>(x, out);
}

// round 16
// speedup vs baseline: 1.1167x; 1.0941x over previous
#include <cuda_runtime.h>
#include <cstdint>

// Problem dims
#define Bv 32
#define Cv 1024
#define Nv 784
#define Mv 4
#define N4v 196      // Nv/4
#define GR 8         // rows per generation
#define GEN 8        // generations per block
#define BROWS 64     // GR*GEN rows per block
#define CHUNKS 16    // Cv/BROWS
#define GSZ (GR * N4v)   // 1568 float4 per generation buffer

// Scratch (device globals)
__device__ float  g_invnorm[Bv][Cv];
__device__ float4 g_tpart[Bv][CHUNKS][Mv][N4v];  // per-chunk partials (6.4 MB)
__device__ float4 g_h[Bv][N4v];                  // h[b,n] = sum_m g/s

__device__ __forceinline__ void cp_async16(uint32_t saddr, const void* gaddr) {
    asm volatile("cp.async.cg.shared.global [%0], [%1], 16;\n" :: "r"(saddr), "l"(gaddr));
}
__device__ __forceinline__ void cp_commit() {
    asm volatile("cp.async.commit_group;\n");
}
template <int N>
__device__ __forceinline__ void cp_wait() {
    asm volatile("cp.async.wait_group %0;\n" :: "n"(N));
}

extern __shared__ float4 smem_dyn[];  // 2 * GSZ float4 = 50176 B

// ---------------------------------------------------------------------------
// kAB: FROZEN from R14 (measured 23.5us, DRAM 57%). Block = (b, 64-row
// chunk), 8 generations of 8 rows, double-buffered cp.async, plain STG flush.
// ---------------------------------------------------------------------------
__global__ void __launch_bounds__(256) kAB(const float* __restrict__ x,
                                           const float* __restrict__ Wm) {
    __shared__ float4 swsc[GR];
    int b = blockIdx.x, ch = blockIdx.y;
    int p0 = ch * BROWS;
    int t = threadIdx.x;
    int warp = t >> 5, lane = t & 31;
    const float4* base = reinterpret_cast<const float4*>(x) + ((size_t)b * Cv + p0) * N4v;
    uint32_t sbase = (uint32_t)__cvta_generic_to_shared(smem_dyn);

    // prefetch generation 0 into buffer 0
#pragma unroll
    for (int k = 0; k < 7; ++k) {
        int i = t + k * 256;
        if (i < GSZ) cp_async16(sbase + i * 16u, base + i);
    }
    cp_commit();

    float4 a0 = {0, 0, 0, 0}, a1 = a0, a2 = a0, a3 = a0;

#pragma unroll
    for (int g = 0; g < GEN; ++g) {
        if (g + 1 < GEN) {
            uint32_t sb = sbase + ((g + 1) & 1) * (GSZ * 16u);
            const float4* gb = base + (g + 1) * GSZ;
#pragma unroll
            for (int k = 0; k < 7; ++k) {
                int i = t + k * 256;
                if (i < GSZ) cp_async16(sb + i * 16u, gb + i);
            }
            cp_commit();
            cp_wait<1>();   // current generation's data is ready
        } else {
            cp_wait<0>();
        }
        __syncthreads();

        float4* cur = smem_dyn + (g & 1) * GSZ;

        // norms: warp w handles row w (8 warps, 8 rows)
        {
            float s = 0.f;
#pragma unroll
            for (int k = 0; k < 7; ++k) {
                int idx = lane + k * 32;
                if (idx < N4v) {
                    float4 v = cur[warp * N4v + idx];
                    s += v.x * v.x + v.y * v.y + v.z * v.z + v.w * v.w;
                }
            }
#pragma unroll
            for (int o = 16; o; o >>= 1) s += __shfl_xor_sync(0xffffffffu, s, o);
            if (lane == 0) {
                float inv = 1.0f / fmaxf(sqrtf(s), 1e-10f);
                int p = p0 + g * GR + warp;
                g_invnorm[b][p] = inv;
                float4 w;
                w.x = Wm[0 * Cv + p] * inv;
                w.y = Wm[1 * Cv + p] * inv;
                w.z = Wm[2 * Cv + p] * inv;
                w.w = Wm[3 * Cv + p] * inv;
                swsc[warp] = w;
            }
        }
        __syncthreads();

        // t-accumulation for this generation's 8 rows
        if (t < N4v) {
#pragma unroll
            for (int r = 0; r < GR; ++r) {
                float4 w  = swsc[r];
                float4 xv = cur[r * N4v + t];
                a0.x = fmaf(w.x, xv.x, a0.x); a0.y = fmaf(w.x, xv.y, a0.y);
                a0.z = fmaf(w.x, xv.z, a0.z); a0.w = fmaf(w.x, xv.w, a0.w);
                a1.x = fmaf(w.y, xv.x, a1.x); a1.y = fmaf(w.y, xv.y, a1.y);
                a1.z = fmaf(w.y, xv.z, a1.z); a1.w = fmaf(w.y, xv.w, a1.w);
                a2.x = fmaf(w.z, xv.x, a2.x); a2.y = fmaf(w.z, xv.y, a2.y);
                a2.z = fmaf(w.z, xv.z, a2.z); a2.w = fmaf(w.z, xv.w, a2.w);
                a3.x = fmaf(w.w, xv.x, a3.x); a3.y = fmaf(w.w, xv.y, a3.y);
                a3.z = fmaf(w.w, xv.z, a3.z); a3.w = fmaf(w.w, xv.w, a3.w);
            }
        }
        __syncthreads();  // buffer fully consumed before next prefetch overwrites
    }

    // plain vectorized store of this block's partials (no atomics)
    if (t < N4v) {
        g_tpart[b][ch][0][t] = a0;
        g_tpart[b][ch][1][t] = a1;
        g_tpart[b][ch][2][t] = a2;
        g_tpart[b][ch][3][t] = a3;
    }
}

// ---------------------------------------------------------------------------
// kC: 896 threads = 4 model-groups x 224 (warp-aligned). Each thread sums
// its 16 chunk partials with 16 INDEPENDENT loads (MLP 16), sigmoid, warp
// reduce of g^2 into per-model sums; group 0 finalizes h.
// ---------------------------------------------------------------------------
__global__ void __launch_bounds__(896) kC() {
    int b = blockIdx.x;
    int t = threadIdx.x;
    int grp = t / 224;       // model index 0..3
    int q   = t % 224;       // quad index (valid < 196)
    bool valid = (q < N4v);
    __shared__ float4 sg[Mv][N4v];
    __shared__ float  sm[Mv];
    if (t < Mv) sm[t] = 0.f;
    __syncthreads();

    float4 g4 = {0, 0, 0, 0};
    if (valid) {
        float4 acc = {0, 0, 0, 0};
#pragma unroll
        for (int c = 0; c < CHUNKS; ++c) {
            float4 v = g_tpart[b][c][grp][q];
            acc.x += v.x; acc.y += v.y; acc.z += v.z; acc.w += v.w;
        }
        g4.x = 1.f / (1.f + __expf(-acc.x));
        g4.y = 1.f / (1.f + __expf(-acc.y));
        g4.z = 1.f / (1.f + __expf(-acc.z));
        g4.w = 1.f / (1.f + __expf(-acc.w));
        sg[grp][q] = g4;
    }
    float ss = g4.x * g4.x + g4.y * g4.y + g4.z * g4.z + g4.w * g4.w;
#pragma unroll
    for (int o = 16; o; o >>= 1) ss += __shfl_xor_sync(0xffffffffu, ss, o);
    if ((t & 31) == 0) atomicAdd(&sm[grp], ss);
    __syncthreads();

    if (grp == 0 && valid) {
        float i0 = 1.f / sm[0], i1 = 1.f / sm[1], i2 = 1.f / sm[2], i3 = 1.f / sm[3];
        float4 v0 = sg[0][q], v1 = sg[1][q], v2 = sg[2][q], v3 = sg[3][q];
        float4 h;
        h.x = v0.x * i0 + v1.x * i1 + v2.x * i2 + v3.x * i3;
        h.y = v0.y * i0 + v1.y * i1 + v2.y * i2 + v3.y * i3;
        h.z = v0.z * i0 + v1.z * i1 + v2.z * i2 + v3.z * i3;
        h.w = v0.w * i0 + v1.w * i1 + v2.w * i2 + v3.w * i3;
        g_h[b][q] = h;
    }
}

// ---------------------------------------------------------------------------
// kD: FROZEN (proven). Barrier-free final dot. Grid (32, 32), 512 threads;
// each warp streams TWO rows interleaved; h via __ldg (L1-hot).
// ---------------------------------------------------------------------------
__global__ void __launch_bounds__(512) kD(const float* __restrict__ x,
                                          float* __restrict__ out) {
    int b = blockIdx.x;
    int warp = threadIdx.x >> 5, lane = threadIdx.x & 31;
    int p = (blockIdx.y << 5) + (warp << 1);   // rows p and p+1
    const float4* r0 = reinterpret_cast<const float4*>(x) + ((size_t)b * Cv + p) * N4v;
    const float4* r1 = r0 + N4v;
    const float4* hb = &g_h[b][0];
    float s0 = 0.f, s1 = 0.f;
#pragma unroll
    for (int k = 0; k < 6; ++k) {
        int idx = lane + k * 32;
        float4 a = r0[idx], c = r1[idx];
        float4 h = __ldg(hb + idx);
        s0 += a.x * h.x + a.y * h.y + a.z * h.z + a.w * h.w;
        s1 += c.x * h.x + c.y * h.y + c.z * h.z + c.w * h.w;
    }
    if (lane < 4) {
        int idx = 192 + lane;
        float4 a = r0[idx], c = r1[idx];
        float4 h = __ldg(hb + idx);
        s0 += a.x * h.x + a.y * h.y + a.z * h.z + a.w * h.w;
        s1 += c.x * h.x + c.y * h.y + c.z * h.z + c.w * h.w;
    }
#pragma unroll
    for (int o = 16; o; o >>= 1) {
        s0 += __shfl_xor_sync(0xffffffffu, s0, o);
        s1 += __shfl_xor_sync(0xffffffffu, s1, o);
    }
    if (lane == 0) {
        out[b * Cv + p]     = s0 * g_invnorm[b][p];
        out[b * Cv + p + 1] = s1 * g_invnorm[b][p + 1];
    }
}

extern "C" void kernel_launch(void* const* d_in, const int* in_sizes, int n_in,
                              void* d_out, int out_size) {
    const float* x  = (const float*)d_in[0];   // [32,1024,28,28] f32
    const float* Wm = (const float*)d_in[1];   // [4,1,1024] f32
    float* out = (float*)d_out;                // [32,1024] f32

    static const int smem_bytes = 2 * GSZ * sizeof(float4);  // 50176
    cudaFuncSetAttribute(kAB, cudaFuncAttributeMaxDynamicSharedMemorySize, smem_bytes);

    kAB<<<dim3(32, CHUNKS), 256, smem_bytes>>>(x, Wm);
    kC<<<32, 896>>>();
    kD<<<dim3(32, 32), 512>>>(x, out);
}